// round 2
// baseline (speedup 1.0000x reference)
#include <cuda_runtime.h>
#include <math.h>

#define SEQ   2048
#define HID   1024
#define THETA 7
#define NBLK_SCAN 64
#define ROWS_PER_CTA (HID / NBLK_SCAN)   // 16

// --- scratch (allocation-free: __device__ globals) ---
__device__ float g_pre0[SEQ * HID];      // 8 MB: pre[0] = x@W_ih^T + internal[0] + b
__device__ float g_h[2][HID];            // double-buffered hidden state
__device__ unsigned int g_ctr;           // grid barrier counter

// ---------------------------------------------------------------------------
// init: zero barrier counter, load initial state. Runs every launch (replay-safe).
// ---------------------------------------------------------------------------
__global__ void init_kernel(const float* __restrict__ state) {
    int t = threadIdx.x;
    if (t == 0) g_ctr = 0u;
    for (int i = t; i < HID; i += blockDim.x) g_h[0][i] = state[i];
}

// ---------------------------------------------------------------------------
// Fused GEMM: C[s][j] = f( sum_i A[s][i]*W[j][i] + addp[s][j] + bih[j] + bhh[j] )
// f = tanh if do_tanh, identity otherwise. If to_pre0, writes g_pre0 instead of C.
// Tiles: 128x128, BK=8, 256 threads, 8x8 microtile.
// ---------------------------------------------------------------------------
__global__ __launch_bounds__(256, 2) void gemm_fused(
    const float* __restrict__ A, const float* __restrict__ W,
    const float* __restrict__ addp, const float* __restrict__ bih,
    const float* __restrict__ bhh, float* __restrict__ C,
    int do_tanh, int to_pre0)
{
    __shared__ float As[8][128];
    __shared__ float Bs[8][128];
    const int tid = threadIdx.x;
    const int M0 = blockIdx.y * 128;
    const int N0 = blockIdx.x * 128;
    const int lr = tid >> 1;          // 0..127 tile row
    const int lc = (tid & 1) << 2;    // 0 or 4 (k offset)
    const int ty = tid >> 4;          // 0..15
    const int tx = tid & 15;          // 0..15

    float acc[8][8];
#pragma unroll
    for (int i = 0; i < 8; i++)
#pragma unroll
        for (int j = 0; j < 8; j++) acc[i][j] = 0.f;

    const float* Ap = A + (size_t)(M0 + lr) * HID + lc;
    const float* Wp = W + (size_t)(N0 + lr) * HID + lc;

    for (int k0 = 0; k0 < HID; k0 += 8) {
        float4 a = *(const float4*)(Ap + k0);
        float4 w = *(const float4*)(Wp + k0);
        As[lc + 0][lr] = a.x; As[lc + 1][lr] = a.y;
        As[lc + 2][lr] = a.z; As[lc + 3][lr] = a.w;
        Bs[lc + 0][lr] = w.x; Bs[lc + 1][lr] = w.y;
        Bs[lc + 2][lr] = w.z; Bs[lc + 3][lr] = w.w;
        __syncthreads();
#pragma unroll
        for (int kk = 0; kk < 8; kk++) {
            float4 a0 = *(const float4*)&As[kk][ty * 8];
            float4 a1 = *(const float4*)&As[kk][ty * 8 + 4];
            float4 b0 = *(const float4*)&Bs[kk][tx * 8];
            float4 b1 = *(const float4*)&Bs[kk][tx * 8 + 4];
            float ar[8] = {a0.x, a0.y, a0.z, a0.w, a1.x, a1.y, a1.z, a1.w};
            float br[8] = {b0.x, b0.y, b0.z, b0.w, b1.x, b1.y, b1.z, b1.w};
#pragma unroll
            for (int i = 0; i < 8; i++)
#pragma unroll
                for (int j = 0; j < 8; j++) acc[i][j] += ar[i] * br[j];
        }
        __syncthreads();
    }

    float* Cp = to_pre0 ? g_pre0 : C;
#pragma unroll
    for (int i = 0; i < 8; i++) {
        int row = M0 + ty * 8 + i;
#pragma unroll
        for (int j = 0; j < 8; j++) {
            int col = N0 + tx * 8 + j;
            size_t idx = (size_t)row * HID + col;
            float v = acc[i][j] + addp[idx] + bih[col] + bhh[col];
            if (do_tanh) v = tanhf(v);
            Cp[idx] = v;
        }
    }
}

// ---------------------------------------------------------------------------
// Sequential base-chain scan. 64 CTAs x 256 threads, persistent.
// CTA b owns rows [b*16, b*16+16) of W_hh, held in registers (64 f32/thread).
// Per step: stage h (L2, __ldcg) -> partial dots -> shfl reduce over 16 lanes
// -> tanh -> write out plane 0 + next h buffer -> grid barrier.
// ---------------------------------------------------------------------------
__global__ __launch_bounds__(256, 1) void scan_kernel(
    const float* __restrict__ W, float* __restrict__ out0,
    float* __restrict__ hT, int write_hT)
{
    const int tid = threadIdx.x;
    const int rlocal = tid >> 4;          // 0..15 row within CTA
    const int lane16 = tid & 15;          // 0..15 chunk within row
    const int j = blockIdx.x * ROWS_PER_CTA + rlocal;
    const int cbase = lane16 * 64;

    float4 wreg[16];
#pragma unroll
    for (int i = 0; i < 16; i++)
        wreg[i] = *(const float4*)&W[(size_t)j * HID + cbase + i * 4];

    __shared__ float hs[HID];

    for (int s = 0; s < SEQ; s++) {
        // stage current h into SMEM (bypass L1: written by other SMs)
        float4 hv = __ldcg((const float4*)&g_h[s & 1][tid * 4]);
        ((float4*)hs)[tid] = hv;
        __syncthreads();

        float acc = 0.f;
#pragma unroll
        for (int i = 0; i < 16; i++) {
            float4 h4 = *(const float4*)&hs[cbase + i * 4];
            acc += wreg[i].x * h4.x + wreg[i].y * h4.y
                 + wreg[i].z * h4.z + wreg[i].w * h4.w;
        }
        acc += __shfl_xor_sync(0xffffffffu, acc, 8);
        acc += __shfl_xor_sync(0xffffffffu, acc, 4);
        acc += __shfl_xor_sync(0xffffffffu, acc, 2);
        acc += __shfl_xor_sync(0xffffffffu, acc, 1);

        if (lane16 == 0) {
            float v = tanhf(g_pre0[(size_t)s * HID + j] + acc);
            out0[(size_t)s * HID + j] = v;
            g_h[(s + 1) & 1][j] = v;
            if (write_hT && s == SEQ - 1) hT[j] = v;
        }

        // grid barrier: release writes, arrive, spin, acquire
        __threadfence();
        __syncthreads();
        if (tid == 0) {
            atomicAdd(&g_ctr, 1u);
            unsigned tgt = (unsigned)(s + 1) * NBLK_SCAN;
            while (*(volatile unsigned int*)&g_ctr < tgt) { }
        }
        __syncthreads();
        __threadfence();
    }
}

// ---------------------------------------------------------------------------
extern "C" void kernel_launch(void* const* d_in, const int* in_sizes, int n_in,
                              void* d_out, int out_size) {
    const float* x        = (const float*)d_in[0];  // [1,2048,1024]
    const float* internal = (const float*)d_in[1];  // [8,2048,1024]
    const float* state    = (const float*)d_in[2];  // [1,1,1024]
    const float* W_ih     = (const float*)d_in[3];  // [1024,1024]
    const float* W_hh     = (const float*)d_in[4];  // [1024,1024]
    const float* b_ih     = (const float*)d_in[5];  // [1024]
    const float* b_hh     = (const float*)d_in[6];  // [1024]
    float* out = (float*)d_out;

    const size_t plane = (size_t)SEQ * HID;
    const int has_tail = (out_size >= (int)((THETA + 1) * plane + HID)) ? 1 : 0;

    init_kernel<<<1, 256>>>(state);

    dim3 gg(HID / 128, SEQ / 128), gb(256);
    // pre0 = x @ W_ih^T + internal[0] + b  (no tanh) -> g_pre0
    gemm_fused<<<gg, gb>>>(x, W_ih, internal, b_ih, b_hh, nullptr,
                           /*do_tanh=*/0, /*to_pre0=*/1);

    // sequential base chain -> out plane 0 (+ hT tail)
    scan_kernel<<<NBLK_SCAN, 256>>>(W_hh, out,
                                    out + (THETA + 1) * plane, has_tail);

    // theta expansion: out[th] = tanh(internal[th] + b + out[th-1] @ W_hh^T)
    for (int th = 1; th <= THETA; th++) {
        gemm_fused<<<gg, gb>>>(out + (size_t)(th - 1) * plane, W_hh,
                               internal + (size_t)th * plane, b_ih, b_hh,
                               out + (size_t)th * plane,
                               /*do_tanh=*/1, /*to_pre0=*/0);
    }
}

// round 10
// speedup vs baseline: 1.7969x; 1.7969x over previous
#include <cuda_runtime.h>
#include <math.h>

#define SEQ   2048
#define HID   1024
#define THETA 7
#define NBLK_SCAN 64
#define ROWS_PER_CTA (HID / NBLK_SCAN)   // 16

// --- scratch (allocation-free: __device__ globals) ---
__device__ float g_pre0[SEQ * HID];      // pre[0] = x@W_ih^T + internal[0] + b
__device__ float g_h[2][HID];            // double-buffered hidden state (plain floats)
__device__ unsigned g_flags[NBLK_SCAN];  // flag[b] = steps completed by CTA b (monotone)

__device__ __forceinline__ unsigned ld_acq(const unsigned* p) {
    unsigned v;
    asm volatile("ld.global.acquire.gpu.u32 %0, [%1];" : "=r"(v) : "l"(p));
    return v;
}
__device__ __forceinline__ void st_rel(unsigned* p, unsigned v) {
    asm volatile("st.global.release.gpu.u32 [%0], %1;" :: "l"(p), "r"(v) : "memory");
}
__device__ __forceinline__ float4 ldcg_f4(const float* p) {
    float4 r;
    asm volatile("ld.global.cg.v4.f32 {%0,%1,%2,%3}, [%4];"
                 : "=f"(r.x), "=f"(r.y), "=f"(r.z), "=f"(r.w) : "l"(p));
    return r;
}
__device__ __forceinline__ void stcg_f(float* p, float v) {
    asm volatile("st.global.cg.f32 [%0], %1;" :: "l"(p), "f"(v) : "memory");
}

// ---------------------------------------------------------------------------
// init: zero all flags, seed h buffer 0. Runs every launch (graph-replay safe).
// ---------------------------------------------------------------------------
__global__ void init_kernel(const float* __restrict__ state) {
    int t = threadIdx.x;                 // 1024 threads
    if (t < NBLK_SCAN) g_flags[t] = 0u;
    g_h[0][t] = state[t];
    g_h[1][t] = 0.f;
}

// ---------------------------------------------------------------------------
// Fused GEMM (verbatim round-2 version, known good):
// C[s][j] = f( sum_i A[s][i]*W[j][i] + addp[s][j] + bih[j] + bhh[j] )
// 128x128 tile, BK=8, 256 threads, 8x8 microtile.
// ---------------------------------------------------------------------------
__global__ __launch_bounds__(256, 2) void gemm_fused(
    const float* __restrict__ A, const float* __restrict__ W,
    const float* __restrict__ addp, const float* __restrict__ bih,
    const float* __restrict__ bhh, float* __restrict__ C,
    int do_tanh, int to_pre0)
{
    __shared__ float As[8][128];
    __shared__ float Bs[8][128];
    const int tid = threadIdx.x;
    const int M0 = blockIdx.y * 128;
    const int N0 = blockIdx.x * 128;
    const int lr = tid >> 1;          // 0..127 tile row
    const int lc = (tid & 1) << 2;    // 0 or 4 (k offset)
    const int ty = tid >> 4;          // 0..15
    const int tx = tid & 15;          // 0..15

    float acc[8][8];
#pragma unroll
    for (int i = 0; i < 8; i++)
#pragma unroll
        for (int j = 0; j < 8; j++) acc[i][j] = 0.f;

    const float* Ap = A + (size_t)(M0 + lr) * HID + lc;
    const float* Wp = W + (size_t)(N0 + lr) * HID + lc;

    for (int k0 = 0; k0 < HID; k0 += 8) {
        float4 a = *(const float4*)(Ap + k0);
        float4 w = *(const float4*)(Wp + k0);
        As[lc + 0][lr] = a.x; As[lc + 1][lr] = a.y;
        As[lc + 2][lr] = a.z; As[lc + 3][lr] = a.w;
        Bs[lc + 0][lr] = w.x; Bs[lc + 1][lr] = w.y;
        Bs[lc + 2][lr] = w.z; Bs[lc + 3][lr] = w.w;
        __syncthreads();
#pragma unroll
        for (int kk = 0; kk < 8; kk++) {
            float4 a0 = *(const float4*)&As[kk][ty * 8];
            float4 a1 = *(const float4*)&As[kk][ty * 8 + 4];
            float4 b0 = *(const float4*)&Bs[kk][tx * 8];
            float4 b1 = *(const float4*)&Bs[kk][tx * 8 + 4];
            float ar[8] = {a0.x, a0.y, a0.z, a0.w, a1.x, a1.y, a1.z, a1.w};
            float br[8] = {b0.x, b0.y, b0.z, b0.w, b1.x, b1.y, b1.z, b1.w};
#pragma unroll
            for (int i = 0; i < 8; i++)
#pragma unroll
                for (int j = 0; j < 8; j++) acc[i][j] += ar[i] * br[j];
        }
        __syncthreads();
    }

    float* Cp = to_pre0 ? g_pre0 : C;
#pragma unroll
    for (int i = 0; i < 8; i++) {
        int row = M0 + ty * 8 + i;
#pragma unroll
        for (int j = 0; j < 8; j++) {
            int col = N0 + tx * 8 + j;
            size_t idx = (size_t)row * HID + col;
            float v = acc[i][j] + addp[idx] + bih[col] + bhh[col];
            if (do_tanh) v = tanhf(v);
            Cp[idx] = v;
        }
    }
}

// ---------------------------------------------------------------------------
// Sequential base-chain scan. 64 CTAs x 256 threads, persistent.
// Release/acquire FLAG-ARRAY barrier (no fences, no atomics, no hot counter):
//   end of step s:  h writes (.cg) -> __syncthreads -> tid0 st.release flag[b]=s+1
//   start of step s: every thread polls 2 of 64 flags (ld.acquire) until >= s
// flags are monotone scalars -> no ABA, no multi-word atomicity assumptions;
// poll-pass at s proves all CTAs completed s-1, making the double-buffer
// overwrite (buf (s+1)&1, last read at s-1) safe.
// CTA b owns rows [b*16, b*16+16); weight chunks strided by 64 cols so the
// SMEM h reads are conflict-free.
// ---------------------------------------------------------------------------
__global__ __launch_bounds__(256, 1) void scan_kernel(
    const float* __restrict__ W, float* __restrict__ out0,
    float* __restrict__ hT, int write_hT)
{
    const int tid = threadIdx.x;
    const int rlocal = tid >> 4;          // 0..15 row within CTA
    const int lane16 = tid & 15;          // 0..15 chunk within row
    const int fl = tid & 31;              // flag index (this thread polls fl, fl+32)
    const int j = blockIdx.x * ROWS_PER_CTA + rlocal;

    // strided weight layout: chunk i covers columns i*64 + lane16*4 .. +3
    float4 wreg[16];
#pragma unroll
    for (int i = 0; i < 16; i++)
        wreg[i] = *(const float4*)&W[(size_t)j * HID + i * 64 + lane16 * 4];

    __shared__ float4 hs4[HID / 4];       // full h, staged per step

    for (int s = 0; s < SEQ; s++) {
        // prefetch pre0 (L2-resident from the GEMM; overlaps the poll)
        float pre = 0.f;
        if (lane16 == 0)
            pre = g_pre0[(size_t)s * HID + j];

        // barrier wait: all 64 flags must reach s (each thread covers 2 flags)
        const unsigned us = (unsigned)s;
        while (ld_acq(&g_flags[fl]) < us) {}
        while (ld_acq(&g_flags[fl + 32]) < us) {}

        // stage h[s] (bypass L1: written by other SMs)
        hs4[tid] = ldcg_f4(&g_h[s & 1][tid * 4]);
        __syncthreads();

        // dot: 4 independent accumulators to break the FMA dependency chain
        float a0 = 0.f, a1 = 0.f, a2 = 0.f, a3 = 0.f;
#pragma unroll
        for (int i = 0; i < 16; i += 4) {
            float4 h0 = hs4[(i + 0) * 16 + lane16];
            float4 h1 = hs4[(i + 1) * 16 + lane16];
            float4 h2 = hs4[(i + 2) * 16 + lane16];
            float4 h3 = hs4[(i + 3) * 16 + lane16];
            a0 += wreg[i + 0].x * h0.x + wreg[i + 0].y * h0.y
                + wreg[i + 0].z * h0.z + wreg[i + 0].w * h0.w;
            a1 += wreg[i + 1].x * h1.x + wreg[i + 1].y * h1.y
                + wreg[i + 1].z * h1.z + wreg[i + 1].w * h1.w;
            a2 += wreg[i + 2].x * h2.x + wreg[i + 2].y * h2.y
                + wreg[i + 2].z * h2.z + wreg[i + 2].w * h2.w;
            a3 += wreg[i + 3].x * h3.x + wreg[i + 3].y * h3.y
                + wreg[i + 3].z * h3.z + wreg[i + 3].w * h3.w;
        }
        float acc = (a0 + a1) + (a2 + a3);
        acc += __shfl_xor_sync(0xffffffffu, acc, 8);
        acc += __shfl_xor_sync(0xffffffffu, acc, 4);
        acc += __shfl_xor_sync(0xffffffffu, acc, 2);
        acc += __shfl_xor_sync(0xffffffffu, acc, 1);

        if (lane16 == 0) {
            float v = tanhf(pre + acc);
            out0[(size_t)s * HID + j] = v;
            stcg_f(&g_h[(s + 1) & 1][j], v);
            if (write_hT && s == SEQ - 1) hT[j] = v;
        }

        // all h writes of this CTA done -> publish progress
        __syncthreads();                     // also protects hs4 for next iter
        if (tid == 0) st_rel(&g_flags[blockIdx.x], us + 1u);
    }
}

// ---------------------------------------------------------------------------
extern "C" void kernel_launch(void* const* d_in, const int* in_sizes, int n_in,
                              void* d_out, int out_size) {
    const float* x        = (const float*)d_in[0];  // [1,2048,1024]
    const float* internal = (const float*)d_in[1];  // [8,2048,1024]
    const float* state    = (const float*)d_in[2];  // [1,1,1024]
    const float* W_ih     = (const float*)d_in[3];  // [1024,1024]
    const float* W_hh     = (const float*)d_in[4];  // [1024,1024]
    const float* b_ih     = (const float*)d_in[5];  // [1024]
    const float* b_hh     = (const float*)d_in[6];  // [1024]
    float* out = (float*)d_out;

    const size_t plane = (size_t)SEQ * HID;
    const int has_tail = (out_size >= (int)((THETA + 1) * plane + HID)) ? 1 : 0;

    init_kernel<<<1, 1024>>>(state);

    dim3 gg(HID / 128, SEQ / 128), gb(256);
    // pre0 = x @ W_ih^T + internal[0] + b  (no tanh) -> g_pre0
    gemm_fused<<<gg, gb>>>(x, W_ih, internal, b_ih, b_hh, nullptr,
                           /*do_tanh=*/0, /*to_pre0=*/1);

    // sequential base chain -> out plane 0 (+ hT tail)
    scan_kernel<<<NBLK_SCAN, 256>>>(W_hh, out,
                                    out + (THETA + 1) * plane, has_tail);

    // theta expansion: out[th] = tanh(internal[th] + b + out[th-1] @ W_hh^T)
    for (int th = 1; th <= THETA; th++) {
        gemm_fused<<<gg, gb>>>(out + (size_t)(th - 1) * plane, W_hh,
                               internal + (size_t)th * plane, b_ih, b_hh,
                               out + (size_t)th * plane,
                               /*do_tanh=*/1, /*to_pre0=*/0);
    }
}

// round 12
// speedup vs baseline: 2.6010x; 1.4475x over previous
#include <cuda_runtime.h>
#include <math.h>

#define SEQ   2048
#define HID   1024
#define THETA 7
#define NBLK_SCAN 64
#define ROWS_PER_CTA (HID / NBLK_SCAN)   // 16
#define FLAG_STRIDE 64                    // 64 u32 = 256B -> one L2 line per flag

// --- scratch (allocation-free: __device__ globals) ---
__device__ float g_pre0[SEQ * HID];      // pre[0] = x@W_ih^T + internal[0] + b
__device__ float g_h[2][HID];            // double-buffered hidden state (plain floats)
__device__ unsigned g_flags[NBLK_SCAN * FLAG_STRIDE];  // flag[b] at b*FLAG_STRIDE (monotone)

__device__ __forceinline__ unsigned ld_acq(const unsigned* p) {
    unsigned v;
    asm volatile("ld.global.acquire.gpu.u32 %0, [%1];" : "=r"(v) : "l"(p));
    return v;
}
__device__ __forceinline__ void st_rel(unsigned* p, unsigned v) {
    asm volatile("st.global.release.gpu.u32 [%0], %1;" :: "l"(p), "r"(v) : "memory");
}
__device__ __forceinline__ float4 ldcg_f4(const float* p) {
    float4 r;
    asm volatile("ld.global.cg.v4.f32 {%0,%1,%2,%3}, [%4];"
                 : "=f"(r.x), "=f"(r.y), "=f"(r.z), "=f"(r.w) : "l"(p));
    return r;
}
__device__ __forceinline__ void stcg_f(float* p, float v) {
    asm volatile("st.global.cg.f32 [%0], %1;" :: "l"(p), "f"(v) : "memory");
}

// ---------------------------------------------------------------------------
// init: zero all (padded) flags, seed h buffer 0. Replay-safe.
// ---------------------------------------------------------------------------
__global__ void init_kernel(const float* __restrict__ state) {
    int t = threadIdx.x;                 // 1024 threads
#pragma unroll
    for (int i = 0; i < NBLK_SCAN * FLAG_STRIDE / 1024; i++)
        g_flags[t + i * 1024] = 0u;
    g_h[0][t] = state[t];
    g_h[1][t] = 0.f;
}

// ---------------------------------------------------------------------------
// Fused GEMM: C[s][j] = f( sum_i A[s][i]*W[j][i] + addp[s][j] + bih[j] + bhh[j] )
// 128x128 tile, BK=16, double-buffered SMEM, register prefetch, 1 sync/iter.
// Correctness of single sync: stores in iter i target buffer nxt_i; the last
// reads of nxt_i happened in iter i-1, before iter i-1's closing sync.
// ---------------------------------------------------------------------------
__global__ __launch_bounds__(256, 1) void gemm_fused(
    const float* __restrict__ A, const float* __restrict__ W,
    const float* __restrict__ addp, const float* __restrict__ bih,
    const float* __restrict__ bhh, float* __restrict__ C,
    int do_tanh, int to_pre0)
{
    __shared__ float As[2][16][128];
    __shared__ float Bs[2][16][128];
    const int tid = threadIdx.x;
    const int M0 = blockIdx.y * 128;
    const int N0 = blockIdx.x * 128;
    const int lr = tid >> 1;            // 0..127 tile row
    const int lc = (tid & 1) << 3;      // 0 or 8 (k offset)
    const int ty = tid >> 4;            // 0..15
    const int tx = tid & 15;            // 0..15

    float acc[8][8];
#pragma unroll
    for (int i = 0; i < 8; i++)
#pragma unroll
        for (int j = 0; j < 8; j++) acc[i][j] = 0.f;

    const float* Ap = A + (size_t)(M0 + lr) * HID + lc;
    const float* Wp = W + (size_t)(N0 + lr) * HID + lc;

    // preload k-tile 0 into buffer 0
    {
        float4 a0 = *(const float4*)(Ap + 0);
        float4 a1 = *(const float4*)(Ap + 4);
        float4 w0 = *(const float4*)(Wp + 0);
        float4 w1 = *(const float4*)(Wp + 4);
        As[0][lc + 0][lr] = a0.x; As[0][lc + 1][lr] = a0.y;
        As[0][lc + 2][lr] = a0.z; As[0][lc + 3][lr] = a0.w;
        As[0][lc + 4][lr] = a1.x; As[0][lc + 5][lr] = a1.y;
        As[0][lc + 6][lr] = a1.z; As[0][lc + 7][lr] = a1.w;
        Bs[0][lc + 0][lr] = w0.x; Bs[0][lc + 1][lr] = w0.y;
        Bs[0][lc + 2][lr] = w0.z; Bs[0][lc + 3][lr] = w0.w;
        Bs[0][lc + 4][lr] = w1.x; Bs[0][lc + 5][lr] = w1.y;
        Bs[0][lc + 6][lr] = w1.z; Bs[0][lc + 7][lr] = w1.w;
    }
    __syncthreads();

    int cur = 0;
    for (int k0 = 0; k0 < HID; k0 += 16) {
        const int has_next = (k0 + 16 < HID);
        float4 a0, a1, w0, w1;
        if (has_next) {
            a0 = *(const float4*)(Ap + k0 + 16);
            a1 = *(const float4*)(Ap + k0 + 20);
            w0 = *(const float4*)(Wp + k0 + 16);
            w1 = *(const float4*)(Wp + k0 + 20);
        }
#pragma unroll
        for (int kk = 0; kk < 16; kk++) {
            float4 af0 = *(const float4*)&As[cur][kk][ty * 8];
            float4 af1 = *(const float4*)&As[cur][kk][ty * 8 + 4];
            float4 bf0 = *(const float4*)&Bs[cur][kk][tx * 8];
            float4 bf1 = *(const float4*)&Bs[cur][kk][tx * 8 + 4];
            float ar[8] = {af0.x, af0.y, af0.z, af0.w, af1.x, af1.y, af1.z, af1.w};
            float br[8] = {bf0.x, bf0.y, bf0.z, bf0.w, bf1.x, bf1.y, bf1.z, bf1.w};
#pragma unroll
            for (int i = 0; i < 8; i++)
#pragma unroll
                for (int j = 0; j < 8; j++) acc[i][j] += ar[i] * br[j];
        }
        if (has_next) {
            const int nxt = cur ^ 1;
            As[nxt][lc + 0][lr] = a0.x; As[nxt][lc + 1][lr] = a0.y;
            As[nxt][lc + 2][lr] = a0.z; As[nxt][lc + 3][lr] = a0.w;
            As[nxt][lc + 4][lr] = a1.x; As[nxt][lc + 5][lr] = a1.y;
            As[nxt][lc + 6][lr] = a1.z; As[nxt][lc + 7][lr] = a1.w;
            Bs[nxt][lc + 0][lr] = w0.x; Bs[nxt][lc + 1][lr] = w0.y;
            Bs[nxt][lc + 2][lr] = w0.z; Bs[nxt][lc + 3][lr] = w0.w;
            Bs[nxt][lc + 4][lr] = w1.x; Bs[nxt][lc + 5][lr] = w1.y;
            Bs[nxt][lc + 6][lr] = w1.z; Bs[nxt][lc + 7][lr] = w1.w;
        }
        __syncthreads();
        cur ^= 1;
    }

    float* Cp = to_pre0 ? g_pre0 : C;
#pragma unroll
    for (int i = 0; i < 8; i++) {
        int row = M0 + ty * 8 + i;
#pragma unroll
        for (int j = 0; j < 8; j++) {
            int col = N0 + tx * 8 + j;
            size_t idx = (size_t)row * HID + col;
            float v = acc[i][j] + addp[idx] + bih[col] + bhh[col];
            if (do_tanh) v = tanhf(v);
            Cp[idx] = v;
        }
    }
}

// ---------------------------------------------------------------------------
// Sequential base-chain scan. 64 CTAs x 256 threads, persistent.
// Flag-array release/acquire barrier, CONTENTION-MINIMIZED:
//   - only warp 0 polls (lane k polls flags k, k+32); __syncthreads releases CTA
//   - flags padded to 256B stride -> each flag on its own L2 line/partition
//   - each flag is polled by exactly 64 warps chip-wide (was: 16K threads/line)
// Monotone scalar flags -> no ABA; poll-pass at s proves all CTAs finished s-1,
// making the double-buffer overwrite (buf (s+1)&1, last read at s-1) safe.
// ---------------------------------------------------------------------------
__global__ __launch_bounds__(256, 1) void scan_kernel(
    const float* __restrict__ W, float* __restrict__ out0,
    float* __restrict__ hT, int write_hT)
{
    const int tid = threadIdx.x;
    const int rlocal = tid >> 4;          // 0..15 row within CTA
    const int lane16 = tid & 15;          // 0..15 chunk within row
    const int j = blockIdx.x * ROWS_PER_CTA + rlocal;

    // strided weight layout: chunk i covers columns i*64 + lane16*4 .. +3
    float4 wreg[16];
#pragma unroll
    for (int i = 0; i < 16; i++)
        wreg[i] = *(const float4*)&W[(size_t)j * HID + i * 64 + lane16 * 4];

    __shared__ float4 hs4[HID / 4];       // full h, staged per step

    for (int s = 0; s < SEQ; s++) {
        // prefetch pre0 (L2-resident from the GEMM; overlaps the wait)
        float pre = 0.f;
        if (lane16 == 0)
            pre = g_pre0[(size_t)s * HID + j];

        // barrier wait: warp 0 polls all 64 flags (2 per lane), others wait at bar
        const unsigned us = (unsigned)s;
        if (tid < 32) {
            while (ld_acq(&g_flags[tid * FLAG_STRIDE]) < us) {}
            while (ld_acq(&g_flags[(tid + 32) * FLAG_STRIDE]) < us) {}
        }
        __syncthreads();                  // acquire + bar => h[s] visible to all

        // stage h[s] (bypass L1: written by other SMs)
        hs4[tid] = ldcg_f4(&g_h[s & 1][tid * 4]);
        __syncthreads();

        // dot: 4 independent accumulators to break the FMA dependency chain
        float a0 = 0.f, a1 = 0.f, a2 = 0.f, a3 = 0.f;
#pragma unroll
        for (int i = 0; i < 16; i += 4) {
            float4 h0 = hs4[(i + 0) * 16 + lane16];
            float4 h1 = hs4[(i + 1) * 16 + lane16];
            float4 h2 = hs4[(i + 2) * 16 + lane16];
            float4 h3 = hs4[(i + 3) * 16 + lane16];
            a0 += wreg[i + 0].x * h0.x + wreg[i + 0].y * h0.y
                + wreg[i + 0].z * h0.z + wreg[i + 0].w * h0.w;
            a1 += wreg[i + 1].x * h1.x + wreg[i + 1].y * h1.y
                + wreg[i + 1].z * h1.z + wreg[i + 1].w * h1.w;
            a2 += wreg[i + 2].x * h2.x + wreg[i + 2].y * h2.y
                + wreg[i + 2].z * h2.z + wreg[i + 2].w * h2.w;
            a3 += wreg[i + 3].x * h3.x + wreg[i + 3].y * h3.y
                + wreg[i + 3].z * h3.z + wreg[i + 3].w * h3.w;
        }
        float acc = (a0 + a1) + (a2 + a3);
        acc += __shfl_xor_sync(0xffffffffu, acc, 8);
        acc += __shfl_xor_sync(0xffffffffu, acc, 4);
        acc += __shfl_xor_sync(0xffffffffu, acc, 2);
        acc += __shfl_xor_sync(0xffffffffu, acc, 1);

        if (lane16 == 0) {
            float v = tanhf(pre + acc);
            out0[(size_t)s * HID + j] = v;
            stcg_f(&g_h[(s + 1) & 1][j], v);
            if (write_hT && s == SEQ - 1) hT[j] = v;
        }

        // all h writes of this CTA done -> publish progress
        __syncthreads();                     // also protects hs4 for next iter
        if (tid == 0) st_rel(&g_flags[blockIdx.x * FLAG_STRIDE], us + 1u);
    }
}

// ---------------------------------------------------------------------------
extern "C" void kernel_launch(void* const* d_in, const int* in_sizes, int n_in,
                              void* d_out, int out_size) {
    const float* x        = (const float*)d_in[0];  // [1,2048,1024]
    const float* internal = (const float*)d_in[1];  // [8,2048,1024]
    const float* state    = (const float*)d_in[2];  // [1,1,1024]
    const float* W_ih     = (const float*)d_in[3];  // [1024,1024]
    const float* W_hh     = (const float*)d_in[4];  // [1024,1024]
    const float* b_ih     = (const float*)d_in[5];  // [1024]
    const float* b_hh     = (const float*)d_in[6];  // [1024]
    float* out = (float*)d_out;

    const size_t plane = (size_t)SEQ * HID;
    const int has_tail = (out_size >= (int)((THETA + 1) * plane + HID)) ? 1 : 0;

    init_kernel<<<1, 1024>>>(state);

    dim3 gg(HID / 128, SEQ / 128), gb(256);
    // pre0 = x @ W_ih^T + internal[0] + b  (no tanh) -> g_pre0
    gemm_fused<<<gg, gb>>>(x, W_ih, internal, b_ih, b_hh, nullptr,
                           /*do_tanh=*/0, /*to_pre0=*/1);

    // sequential base chain -> out plane 0 (+ hT tail)
    scan_kernel<<<NBLK_SCAN, 256>>>(W_hh, out,
                                    out + (THETA + 1) * plane, has_tail);

    // theta expansion: out[th] = tanh(internal[th] + b + out[th-1] @ W_hh^T)
    for (int th = 1; th <= THETA; th++) {
        gemm_fused<<<gg, gb>>>(out + (size_t)(th - 1) * plane, W_hh,
                               internal + (size_t)th * plane, b_ih, b_hh,
                               out + (size_t)th * plane,
                               /*do_tanh=*/1, /*to_pre0=*/0);
    }
}

// round 13
// speedup vs baseline: 2.8258x; 1.0864x over previous
#include <cuda_runtime.h>
#include <math.h>

#define SEQ   2048
#define HID   1024
#define THETA 7
#define NBLK_SCAN 64
#define ROWS_PER_CTA (HID / NBLK_SCAN)   // 16
#define FLAG_STRIDE 64                    // 64 u32 = 256B -> one L2 line per flag

// --- scratch (allocation-free: __device__ globals) ---
__device__ float g_pre0[SEQ * HID];      // pre[0] = x@W_ih^T + internal[0] + b
__device__ float g_h[2][HID];            // double-buffered hidden state (plain floats)
__device__ unsigned g_flags[NBLK_SCAN * FLAG_STRIDE];  // flag[b] at b*FLAG_STRIDE (monotone)

__device__ __forceinline__ unsigned ld_acq(const unsigned* p) {
    unsigned v;
    asm volatile("ld.global.acquire.gpu.u32 %0, [%1];" : "=r"(v) : "l"(p));
    return v;
}
__device__ __forceinline__ void st_rel(unsigned* p, unsigned v) {
    asm volatile("st.global.release.gpu.u32 [%0], %1;" :: "l"(p), "r"(v) : "memory");
}
__device__ __forceinline__ float4 ldcg_f4(const float* p) {
    float4 r;
    asm volatile("ld.global.cg.v4.f32 {%0,%1,%2,%3}, [%4];"
                 : "=f"(r.x), "=f"(r.y), "=f"(r.z), "=f"(r.w) : "l"(p));
    return r;
}
__device__ __forceinline__ void stcg_f(float* p, float v) {
    asm volatile("st.global.cg.f32 [%0], %1;" :: "l"(p), "f"(v) : "memory");
}

// ---------------------------------------------------------------------------
// init: zero all (padded) flags, seed h buffer 0. Replay-safe.
// ---------------------------------------------------------------------------
__global__ void init_kernel(const float* __restrict__ state) {
    int t = threadIdx.x;                 // 1024 threads
#pragma unroll
    for (int i = 0; i < NBLK_SCAN * FLAG_STRIDE / 1024; i++)
        g_flags[t + i * 1024] = 0u;
    g_h[0][t] = state[t];
    g_h[1][t] = 0.f;
}

// ---------------------------------------------------------------------------
// Fused GEMM: C[s][j] = f( sum_i A[s][i]*W[j][i] + addp[s][j] + bih[j] + bhh[j] )
// 128x128 tile, BK=16, double-buffered SMEM, register prefetch, 1 sync/iter.
// (unchanged from round 12 — measured at ~94% of the f32 FFMA roofline)
// ---------------------------------------------------------------------------
__global__ __launch_bounds__(256, 1) void gemm_fused(
    const float* __restrict__ A, const float* __restrict__ W,
    const float* __restrict__ addp, const float* __restrict__ bih,
    const float* __restrict__ bhh, float* __restrict__ C,
    int do_tanh, int to_pre0)
{
    __shared__ float As[2][16][128];
    __shared__ float Bs[2][16][128];
    const int tid = threadIdx.x;
    const int M0 = blockIdx.y * 128;
    const int N0 = blockIdx.x * 128;
    const int lr = tid >> 1;            // 0..127 tile row
    const int lc = (tid & 1) << 3;      // 0 or 8 (k offset)
    const int ty = tid >> 4;            // 0..15
    const int tx = tid & 15;            // 0..15

    float acc[8][8];
#pragma unroll
    for (int i = 0; i < 8; i++)
#pragma unroll
        for (int j = 0; j < 8; j++) acc[i][j] = 0.f;

    const float* Ap = A + (size_t)(M0 + lr) * HID + lc;
    const float* Wp = W + (size_t)(N0 + lr) * HID + lc;

    // preload k-tile 0 into buffer 0
    {
        float4 a0 = *(const float4*)(Ap + 0);
        float4 a1 = *(const float4*)(Ap + 4);
        float4 w0 = *(const float4*)(Wp + 0);
        float4 w1 = *(const float4*)(Wp + 4);
        As[0][lc + 0][lr] = a0.x; As[0][lc + 1][lr] = a0.y;
        As[0][lc + 2][lr] = a0.z; As[0][lc + 3][lr] = a0.w;
        As[0][lc + 4][lr] = a1.x; As[0][lc + 5][lr] = a1.y;
        As[0][lc + 6][lr] = a1.z; As[0][lc + 7][lr] = a1.w;
        Bs[0][lc + 0][lr] = w0.x; Bs[0][lc + 1][lr] = w0.y;
        Bs[0][lc + 2][lr] = w0.z; Bs[0][lc + 3][lr] = w0.w;
        Bs[0][lc + 4][lr] = w1.x; Bs[0][lc + 5][lr] = w1.y;
        Bs[0][lc + 6][lr] = w1.z; Bs[0][lc + 7][lr] = w1.w;
    }
    __syncthreads();

    int cur = 0;
    for (int k0 = 0; k0 < HID; k0 += 16) {
        const int has_next = (k0 + 16 < HID);
        float4 a0, a1, w0, w1;
        if (has_next) {
            a0 = *(const float4*)(Ap + k0 + 16);
            a1 = *(const float4*)(Ap + k0 + 20);
            w0 = *(const float4*)(Wp + k0 + 16);
            w1 = *(const float4*)(Wp + k0 + 20);
        }
#pragma unroll
        for (int kk = 0; kk < 16; kk++) {
            float4 af0 = *(const float4*)&As[cur][kk][ty * 8];
            float4 af1 = *(const float4*)&As[cur][kk][ty * 8 + 4];
            float4 bf0 = *(const float4*)&Bs[cur][kk][tx * 8];
            float4 bf1 = *(const float4*)&Bs[cur][kk][tx * 8 + 4];
            float ar[8] = {af0.x, af0.y, af0.z, af0.w, af1.x, af1.y, af1.z, af1.w};
            float br[8] = {bf0.x, bf0.y, bf0.z, bf0.w, bf1.x, bf1.y, bf1.z, bf1.w};
#pragma unroll
            for (int i = 0; i < 8; i++)
#pragma unroll
                for (int j = 0; j < 8; j++) acc[i][j] += ar[i] * br[j];
        }
        if (has_next) {
            const int nxt = cur ^ 1;
            As[nxt][lc + 0][lr] = a0.x; As[nxt][lc + 1][lr] = a0.y;
            As[nxt][lc + 2][lr] = a0.z; As[nxt][lc + 3][lr] = a0.w;
            As[nxt][lc + 4][lr] = a1.x; As[nxt][lc + 5][lr] = a1.y;
            As[nxt][lc + 6][lr] = a1.z; As[nxt][lc + 7][lr] = a1.w;
            Bs[nxt][lc + 0][lr] = w0.x; Bs[nxt][lc + 1][lr] = w0.y;
            Bs[nxt][lc + 2][lr] = w0.z; Bs[nxt][lc + 3][lr] = w0.w;
            Bs[nxt][lc + 4][lr] = w1.x; Bs[nxt][lc + 5][lr] = w1.y;
            Bs[nxt][lc + 6][lr] = w1.z; Bs[nxt][lc + 7][lr] = w1.w;
        }
        __syncthreads();
        cur ^= 1;
    }

    float* Cp = to_pre0 ? g_pre0 : C;
#pragma unroll
    for (int i = 0; i < 8; i++) {
        int row = M0 + ty * 8 + i;
#pragma unroll
        for (int j = 0; j < 8; j++) {
            int col = N0 + tx * 8 + j;
            size_t idx = (size_t)row * HID + col;
            float v = acc[i][j] + addp[idx] + bih[col] + bhh[col];
            if (do_tanh) v = tanhf(v);
            Cp[idx] = v;
        }
    }
}

// ---------------------------------------------------------------------------
// Sequential base-chain scan. 64 CTAs x 256 threads, persistent.
// Flag-array release/acquire barrier (monotone per-CTA flags, 256B-strided).
// Round-13 chain surgery:
//   (a) out0 STG moved AFTER the flag release -> release now orders only the
//       16 h stores (64B), not the DRAM-bound output-plane store.
//   (b) both flag polls issued back-to-back (MLP=2) before refining.
//   (c) pre0[s+1] prefetched during step s compute.
// ---------------------------------------------------------------------------
__global__ __launch_bounds__(256, 1) void scan_kernel(
    const float* __restrict__ W, float* __restrict__ out0,
    float* __restrict__ hT, int write_hT)
{
    const int tid = threadIdx.x;
    const int rlocal = tid >> 4;          // 0..15 row within CTA
    const int lane16 = tid & 15;          // 0..15 chunk within row
    const int j = blockIdx.x * ROWS_PER_CTA + rlocal;

    // strided weight layout: chunk i covers columns i*64 + lane16*4 .. +3
    float4 wreg[16];
#pragma unroll
    for (int i = 0; i < 16; i++)
        wreg[i] = *(const float4*)&W[(size_t)j * HID + i * 64 + lane16 * 4];

    __shared__ float4 hs4[HID / 4];       // full h, staged per step

    // pre0 for step 0, held across the wait
    float pre = 0.f;
    if (lane16 == 0)
        pre = g_pre0[j];

    for (int s = 0; s < SEQ; s++) {
        // barrier wait: warp 0 polls all 64 flags (2 per lane, issued together)
        const unsigned us = (unsigned)s;
        if (tid < 32) {
            const unsigned* f0 = &g_flags[tid * FLAG_STRIDE];
            const unsigned* f1 = &g_flags[(tid + 32) * FLAG_STRIDE];
            unsigned a = ld_acq(f0);
            unsigned b = ld_acq(f1);
            while (a < us) a = ld_acq(f0);
            while (b < us) b = ld_acq(f1);
        }
        __syncthreads();                  // acquire + bar => h[s] visible to all

        // stage h[s] (bypass L1: written by other SMs)
        hs4[tid] = ldcg_f4(&g_h[s & 1][tid * 4]);
        __syncthreads();

        // prefetch pre0 for next step (hides its L2 latency behind compute)
        float pre_next = 0.f;
        if (lane16 == 0 && s + 1 < SEQ)
            pre_next = g_pre0[(size_t)(s + 1) * HID + j];

        // dot: 4 independent accumulators to break the FMA dependency chain
        float a0 = 0.f, a1 = 0.f, a2 = 0.f, a3 = 0.f;
#pragma unroll
        for (int i = 0; i < 16; i += 4) {
            float4 h0 = hs4[(i + 0) * 16 + lane16];
            float4 h1 = hs4[(i + 1) * 16 + lane16];
            float4 h2 = hs4[(i + 2) * 16 + lane16];
            float4 h3 = hs4[(i + 3) * 16 + lane16];
            a0 += wreg[i + 0].x * h0.x + wreg[i + 0].y * h0.y
                + wreg[i + 0].z * h0.z + wreg[i + 0].w * h0.w;
            a1 += wreg[i + 1].x * h1.x + wreg[i + 1].y * h1.y
                + wreg[i + 1].z * h1.z + wreg[i + 1].w * h1.w;
            a2 += wreg[i + 2].x * h2.x + wreg[i + 2].y * h2.y
                + wreg[i + 2].z * h2.z + wreg[i + 2].w * h2.w;
            a3 += wreg[i + 3].x * h3.x + wreg[i + 3].y * h3.y
                + wreg[i + 3].z * h3.z + wreg[i + 3].w * h3.w;
        }
        float acc = (a0 + a1) + (a2 + a3);
        acc += __shfl_xor_sync(0xffffffffu, acc, 8);
        acc += __shfl_xor_sync(0xffffffffu, acc, 4);
        acc += __shfl_xor_sync(0xffffffffu, acc, 2);
        acc += __shfl_xor_sync(0xffffffffu, acc, 1);

        float v = 0.f;
        if (lane16 == 0) {
            v = tanhf(pre + acc);
            stcg_f(&g_h[(s + 1) & 1][j], v);   // ONLY the h store precedes release
        }

        __syncthreads();                       // h stores done; protects hs4 too
        if (tid == 0) st_rel(&g_flags[blockIdx.x * FLAG_STRIDE], us + 1u);

        // output-plane store AFTER the release: off the synchronization chain
        if (lane16 == 0) {
            out0[(size_t)s * HID + j] = v;
            if (write_hT && s == SEQ - 1) hT[j] = v;
        }
        pre = pre_next;
    }
}

// ---------------------------------------------------------------------------
extern "C" void kernel_launch(void* const* d_in, const int* in_sizes, int n_in,
                              void* d_out, int out_size) {
    const float* x        = (const float*)d_in[0];  // [1,2048,1024]
    const float* internal = (const float*)d_in[1];  // [8,2048,1024]
    const float* state    = (const float*)d_in[2];  // [1,1,1024]
    const float* W_ih     = (const float*)d_in[3];  // [1024,1024]
    const float* W_hh     = (const float*)d_in[4];  // [1024,1024]
    const float* b_ih     = (const float*)d_in[5];  // [1024]
    const float* b_hh     = (const float*)d_in[6];  // [1024]
    float* out = (float*)d_out;

    const size_t plane = (size_t)SEQ * HID;
    const int has_tail = (out_size >= (int)((THETA + 1) * plane + HID)) ? 1 : 0;

    init_kernel<<<1, 1024>>>(state);

    dim3 gg(HID / 128, SEQ / 128), gb(256);
    // pre0 = x @ W_ih^T + internal[0] + b  (no tanh) -> g_pre0
    gemm_fused<<<gg, gb>>>(x, W_ih, internal, b_ih, b_hh, nullptr,
                           /*do_tanh=*/0, /*to_pre0=*/1);

    // sequential base chain -> out plane 0 (+ hT tail)
    scan_kernel<<<NBLK_SCAN, 256>>>(W_hh, out,
                                    out + (THETA + 1) * plane, has_tail);

    // theta expansion: out[th] = tanh(internal[th] + b + out[th-1] @ W_hh^T)
    for (int th = 1; th <= THETA; th++) {
        gemm_fused<<<gg, gb>>>(out + (size_t)(th - 1) * plane, W_hh,
                               internal + (size_t)th * plane, b_ih, b_hh,
                               out + (size_t)th * plane,
                               /*do_tanh=*/1, /*to_pre0=*/0);
    }
}

// round 14
// speedup vs baseline: 3.7913x; 1.3417x over previous
#include <cuda_runtime.h>
#include <math.h>

#define SEQ   2048
#define HID   1024
#define THETA 7
#define NBLK_SCAN 64
#define ROWS_PER_CTA (HID / NBLK_SCAN)   // 16

// --- scratch (allocation-free: __device__ globals) ---
__device__ float g_pre0[SEQ * HID];                 // pre[0] = x@W_ih^T + internal[0] + b
__device__ unsigned long long g_hp[2][HID];         // packed (tag:u32 << 32 | value:f32bits),
                                                    // double-buffered; single 8B atomic word
                                                    // => data is its own flag, 1 RT per step.

__device__ __forceinline__ unsigned long long ld_rlx64(const unsigned long long* p) {
    unsigned long long v;
    asm volatile("ld.global.relaxed.gpu.b64 %0, [%1];" : "=l"(v) : "l"(p));
    return v;
}
__device__ __forceinline__ void st_rlx64(unsigned long long* p, unsigned long long v) {
    asm volatile("st.global.relaxed.gpu.b64 [%0], %1;" :: "l"(p), "l"(v) : "memory");
}

// ---------------------------------------------------------------------------
// init: buffer0 = (tag 0, state), buffer1 = (tag INVALID, 0). Replay-safe:
// every slot of both buffers is rewritten on every launch.
// ---------------------------------------------------------------------------
__global__ void init_kernel(const float* __restrict__ state) {
    int i = threadIdx.x;                 // 1024 threads
    g_hp[0][i] = (unsigned long long)__float_as_uint(state[i]);          // tag 0
    g_hp[1][i] = 0xFFFFFFFF00000000ull;                                  // tag INVALID
}

// ---------------------------------------------------------------------------
// Fused GEMM: C[s][j] = f( sum_i A[s][i]*W[j][i] + addp[s][j] + bih[j] + bhh[j] )
// 128x128 tile, BK=16, double-buffered SMEM, register prefetch, 1 sync/iter.
// (unchanged — measured at ~94% of the f32 FFMA roofline)
// ---------------------------------------------------------------------------
__global__ __launch_bounds__(256, 1) void gemm_fused(
    const float* __restrict__ A, const float* __restrict__ W,
    const float* __restrict__ addp, const float* __restrict__ bih,
    const float* __restrict__ bhh, float* __restrict__ C,
    int do_tanh, int to_pre0)
{
    __shared__ float As[2][16][128];
    __shared__ float Bs[2][16][128];
    const int tid = threadIdx.x;
    const int M0 = blockIdx.y * 128;
    const int N0 = blockIdx.x * 128;
    const int lr = tid >> 1;            // 0..127 tile row
    const int lc = (tid & 1) << 3;      // 0 or 8 (k offset)
    const int ty = tid >> 4;            // 0..15
    const int tx = tid & 15;            // 0..15

    float acc[8][8];
#pragma unroll
    for (int i = 0; i < 8; i++)
#pragma unroll
        for (int j = 0; j < 8; j++) acc[i][j] = 0.f;

    const float* Ap = A + (size_t)(M0 + lr) * HID + lc;
    const float* Wp = W + (size_t)(N0 + lr) * HID + lc;

    // preload k-tile 0 into buffer 0
    {
        float4 a0 = *(const float4*)(Ap + 0);
        float4 a1 = *(const float4*)(Ap + 4);
        float4 w0 = *(const float4*)(Wp + 0);
        float4 w1 = *(const float4*)(Wp + 4);
        As[0][lc + 0][lr] = a0.x; As[0][lc + 1][lr] = a0.y;
        As[0][lc + 2][lr] = a0.z; As[0][lc + 3][lr] = a0.w;
        As[0][lc + 4][lr] = a1.x; As[0][lc + 5][lr] = a1.y;
        As[0][lc + 6][lr] = a1.z; As[0][lc + 7][lr] = a1.w;
        Bs[0][lc + 0][lr] = w0.x; Bs[0][lc + 1][lr] = w0.y;
        Bs[0][lc + 2][lr] = w0.z; Bs[0][lc + 3][lr] = w0.w;
        Bs[0][lc + 4][lr] = w1.x; Bs[0][lc + 5][lr] = w1.y;
        Bs[0][lc + 6][lr] = w1.z; Bs[0][lc + 7][lr] = w1.w;
    }
    __syncthreads();

    int cur = 0;
    for (int k0 = 0; k0 < HID; k0 += 16) {
        const int has_next = (k0 + 16 < HID);
        float4 a0, a1, w0, w1;
        if (has_next) {
            a0 = *(const float4*)(Ap + k0 + 16);
            a1 = *(const float4*)(Ap + k0 + 20);
            w0 = *(const float4*)(Wp + k0 + 16);
            w1 = *(const float4*)(Wp + k0 + 20);
        }
#pragma unroll
        for (int kk = 0; kk < 16; kk++) {
            float4 af0 = *(const float4*)&As[cur][kk][ty * 8];
            float4 af1 = *(const float4*)&As[cur][kk][ty * 8 + 4];
            float4 bf0 = *(const float4*)&Bs[cur][kk][tx * 8];
            float4 bf1 = *(const float4*)&Bs[cur][kk][tx * 8 + 4];
            float ar[8] = {af0.x, af0.y, af0.z, af0.w, af1.x, af1.y, af1.z, af1.w};
            float br[8] = {bf0.x, bf0.y, bf0.z, bf0.w, bf1.x, bf1.y, bf1.z, bf1.w};
#pragma unroll
            for (int i = 0; i < 8; i++)
#pragma unroll
                for (int j = 0; j < 8; j++) acc[i][j] += ar[i] * br[j];
        }
        if (has_next) {
            const int nxt = cur ^ 1;
            As[nxt][lc + 0][lr] = a0.x; As[nxt][lc + 1][lr] = a0.y;
            As[nxt][lc + 2][lr] = a0.z; As[nxt][lc + 3][lr] = a0.w;
            As[nxt][lc + 4][lr] = a1.x; As[nxt][lc + 5][lr] = a1.y;
            As[nxt][lc + 6][lr] = a1.z; As[nxt][lc + 7][lr] = a1.w;
            Bs[nxt][lc + 0][lr] = w0.x; Bs[nxt][lc + 1][lr] = w0.y;
            Bs[nxt][lc + 2][lr] = w0.z; Bs[nxt][lc + 3][lr] = w0.w;
            Bs[nxt][lc + 4][lr] = w1.x; Bs[nxt][lc + 5][lr] = w1.y;
            Bs[nxt][lc + 6][lr] = w1.z; Bs[nxt][lc + 7][lr] = w1.w;
        }
        __syncthreads();
        cur ^= 1;
    }

    float* Cp = to_pre0 ? g_pre0 : C;
#pragma unroll
    for (int i = 0; i < 8; i++) {
        int row = M0 + ty * 8 + i;
#pragma unroll
        for (int j = 0; j < 8; j++) {
            int col = N0 + tx * 8 + j;
            size_t idx = (size_t)row * HID + col;
            float v = acc[i][j] + addp[idx] + bih[col] + bhh[col];
            if (do_tanh) v = tanhf(v);
            Cp[idx] = v;
        }
    }
}

// ---------------------------------------------------------------------------
// Sequential base-chain scan. 64 CTAs x 256 threads, persistent.
// ONE-ROUND-TRIP sync: each h element is an 8-byte atomic word (tag|value).
//   producer (lane16==0): tanh -> st.relaxed.gpu.b64 (tag s+1 | value)
//   consumer: each thread polls its OWN 4 words with ld.relaxed.gpu.b64 until
//             all tags == s; value arrives in the same atomic word -> no fence,
//             no flag array, no pre-release __syncthreads.
// Monotone per-slot tags (0,2,4.. / 1,3,5..) -> exact-match poll, no ABA;
// overwrite of tag s-1 by s+1 can only happen after every CTA wrote tag s,
// i.e. after every CTA finished reading s-1. Init rewrites both buffers.
// ---------------------------------------------------------------------------
__global__ __launch_bounds__(256, 1) void scan_kernel(
    const float* __restrict__ W, float* __restrict__ out0,
    float* __restrict__ hT, int write_hT)
{
    const int tid = threadIdx.x;
    const int rlocal = tid >> 4;          // 0..15 row within CTA
    const int lane16 = tid & 15;          // 0..15 chunk within row
    const int j = blockIdx.x * ROWS_PER_CTA + rlocal;

    // strided weight layout: chunk i covers columns i*64 + lane16*4 .. +3
    float4 wreg[16];
#pragma unroll
    for (int i = 0; i < 16; i++)
        wreg[i] = *(const float4*)&W[(size_t)j * HID + i * 64 + lane16 * 4];

    __shared__ float4 hs4[HID / 4];       // full h, staged per step

    // pre0 for step 0, held across the wait
    float pre = 0.f;
    if (lane16 == 0)
        pre = g_pre0[j];

    for (int s = 0; s < SEQ; s++) {
        // poll this thread's 4 packed words until all carry tag s (MLP=4)
        const unsigned long long* base = &g_hp[s & 1][tid * 4];
        const unsigned tag = (unsigned)s;
        unsigned long long w0, w1, w2, w3;
        for (;;) {
            w0 = ld_rlx64(base + 0);
            w1 = ld_rlx64(base + 1);
            w2 = ld_rlx64(base + 2);
            w3 = ld_rlx64(base + 3);
            if (((unsigned)(w0 >> 32) == tag) & ((unsigned)(w1 >> 32) == tag) &
                ((unsigned)(w2 >> 32) == tag) & ((unsigned)(w3 >> 32) == tag))
                break;
        }
        hs4[tid] = make_float4(__uint_as_float((unsigned)w0),
                               __uint_as_float((unsigned)w1),
                               __uint_as_float((unsigned)w2),
                               __uint_as_float((unsigned)w3));
        __syncthreads();

        // prefetch pre0 for next step (hides its L2 latency behind compute)
        float pre_next = 0.f;
        if (lane16 == 0 && s + 1 < SEQ)
            pre_next = g_pre0[(size_t)(s + 1) * HID + j];

        // dot: 4 independent accumulators to break the FMA dependency chain
        float a0 = 0.f, a1 = 0.f, a2 = 0.f, a3 = 0.f;
#pragma unroll
        for (int i = 0; i < 16; i += 4) {
            float4 h0 = hs4[(i + 0) * 16 + lane16];
            float4 h1 = hs4[(i + 1) * 16 + lane16];
            float4 h2 = hs4[(i + 2) * 16 + lane16];
            float4 h3 = hs4[(i + 3) * 16 + lane16];
            a0 += wreg[i + 0].x * h0.x + wreg[i + 0].y * h0.y
                + wreg[i + 0].z * h0.z + wreg[i + 0].w * h0.w;
            a1 += wreg[i + 1].x * h1.x + wreg[i + 1].y * h1.y
                + wreg[i + 1].z * h1.z + wreg[i + 1].w * h1.w;
            a2 += wreg[i + 2].x * h2.x + wreg[i + 2].y * h2.y
                + wreg[i + 2].z * h2.z + wreg[i + 2].w * h2.w;
            a3 += wreg[i + 3].x * h3.x + wreg[i + 3].y * h3.y
                + wreg[i + 3].z * h3.z + wreg[i + 3].w * h3.w;
        }
        float acc = (a0 + a1) + (a2 + a3);
        acc += __shfl_xor_sync(0xffffffffu, acc, 8);
        acc += __shfl_xor_sync(0xffffffffu, acc, 4);
        acc += __shfl_xor_sync(0xffffffffu, acc, 2);
        acc += __shfl_xor_sync(0xffffffffu, acc, 1);

        float v = 0.f;
        if (lane16 == 0) {
            v = tanhf(pre + acc);
            // single 8B atomic word: tag (s+1) | value — THE sync event
            st_rlx64(&g_hp[(s + 1) & 1][j],
                     ((unsigned long long)(unsigned)(s + 1) << 32) |
                      (unsigned long long)__float_as_uint(v));
        }

        // output-plane store: entirely off the synchronization chain
        if (lane16 == 0) {
            out0[(size_t)s * HID + j] = v;
            if (write_hT && s == SEQ - 1) hT[j] = v;
        }
        pre = pre_next;
        __syncthreads();                 // protect hs4 before next overwrite
    }
}

// ---------------------------------------------------------------------------
extern "C" void kernel_launch(void* const* d_in, const int* in_sizes, int n_in,
                              void* d_out, int out_size) {
    const float* x        = (const float*)d_in[0];  // [1,2048,1024]
    const float* internal = (const float*)d_in[1];  // [8,2048,1024]
    const float* state    = (const float*)d_in[2];  // [1,1,1024]
    const float* W_ih     = (const float*)d_in[3];  // [1024,1024]
    const float* W_hh     = (const float*)d_in[4];  // [1024,1024]
    const float* b_ih     = (const float*)d_in[5];  // [1024]
    const float* b_hh     = (const float*)d_in[6];  // [1024]
    float* out = (float*)d_out;

    const size_t plane = (size_t)SEQ * HID;
    const int has_tail = (out_size >= (int)((THETA + 1) * plane + HID)) ? 1 : 0;

    init_kernel<<<1, 1024>>>(state);

    dim3 gg(HID / 128, SEQ / 128), gb(256);
    // pre0 = x @ W_ih^T + internal[0] + b  (no tanh) -> g_pre0
    gemm_fused<<<gg, gb>>>(x, W_ih, internal, b_ih, b_hh, nullptr,
                           /*do_tanh=*/0, /*to_pre0=*/1);

    // sequential base chain -> out plane 0 (+ hT tail)
    scan_kernel<<<NBLK_SCAN, 256>>>(W_hh, out,
                                    out + (THETA + 1) * plane, has_tail);

    // theta expansion: out[th] = tanh(internal[th] + b + out[th-1] @ W_hh^T)
    for (int th = 1; th <= THETA; th++) {
        gemm_fused<<<gg, gb>>>(out + (size_t)(th - 1) * plane, W_hh,
                               internal + (size_t)th * plane, b_ih, b_hh,
                               out + (size_t)th * plane,
                               /*do_tanh=*/1, /*to_pre0=*/0);
    }
}